// round 16
// baseline (speedup 1.0000x reference)
#include <cuda_runtime.h>
#include <cuda_fp16.h>
#include <mma.h>
#include <float.h>

using namespace nvcuda;

// Problem constants (fixed by reference setup_inputs)
#define LN   1024      // sequence length L
#define DD   768       // hidden d
#define HH   12        // heads
#define EE   32        // entities
#define MM   4         // mentions
#define RR   256       // relations per doc
#define NMAX 4         // batch

// Scratch (device globals -- no allocation allowed)
__device__ float g_e_emb[NMAX * EE * DD];                        // (n,E,d)
__device__ __align__(16) __half g_e_att[NMAX * EE * HH * LN];    // (n,E,h,L) fp16
__device__ __align__(16) __half g_A[NMAX * RR * LN];             // ht_att fp16
__device__ __align__(16) __half g_B[NMAX * LN * DD];             // seq fp16

// ---------------------------------------------------------------------------
// Kernel 1: e_att gather (1 float4/thread, max blocks for latency) || e_emb.
// ---------------------------------------------------------------------------
#define NB_EATT  ((NMAX * EE * HH * (LN / 4)) / 256)        // 1536
#define NB_EMB   ((NMAX * EE * DD) / 256)                   // 384

__global__ void k_eatt(const float* __restrict__ seq,
                       const float* __restrict__ att,
                       const int*   __restrict__ pos,
                       const float* __restrict__ mask,
                       int n)
{
    int blk = blockIdx.x;
    if (blk < NB_EATT) {
        // ---- e_att: one float4 per thread, 4 independent mention LDGs ----
        int idx = blk * 256 + threadIdx.x;
        int total = n * EE * HH * (LN / 4);
        if (idx >= total) return;
        int l4 = idx % (LN / 4);
        int hh = (idx / (LN / 4)) % HH;
        int e  = (idx / ((LN / 4) * HH)) % EE;
        int i  = idx / ((LN / 4) * HH * EE);
        const int4   p4 = *(const int4*)  (pos  + (i * EE + e) * MM);
        const float4 m4 = *(const float4*)(mask + (i * EE + e) * MM);
        const float4* att4 = (const float4*)att;
        int   pp[MM] = {p4.x + 1, p4.y + 1, p4.z + 1, p4.w + 1};
        float mk[MM] = {m4.x, m4.y, m4.z, m4.w};
        float cnt = mk[0] + mk[1] + mk[2] + mk[3];
        float4 s = make_float4(0.f, 0.f, 0.f, 0.f);
#pragma unroll
        for (int m = 0; m < MM; m++) {
            float4 a = att4[((size_t)(i * HH + hh) * LN + pp[m]) * (LN / 4) + l4];
            s.x += mk[m] * a.x; s.y += mk[m] * a.y;
            s.z += mk[m] * a.z; s.w += mk[m] * a.w;
        }
        float inv = 1.0f / fmaxf(cnt, 1.0f);
        __half2 h01 = __floats2half2_rn(s.x * inv, s.y * inv);
        __half2 h23 = __floats2half2_rn(s.z * inv, s.w * inv);
        uint2 w;
        w.x = *(unsigned*)&h01;
        w.y = *(unsigned*)&h23;
        ((uint2*)g_e_att)[idx] = w;
    } else {
        // ---- e_emb ----
        int idx = (blk - NB_EATT) * 256 + threadIdx.x;
        int total = n * EE * DD;
        if (idx >= total) return;
        int k = idx % DD;
        int e = (idx / DD) % EE;
        int i = idx / (DD * EE);
        const int*   p  = pos  + (i * EE + e) * MM;
        const float* mk = mask + (i * EE + e) * MM;
        float v[MM];
        float mx = -FLT_MAX;
#pragma unroll
        for (int m = 0; m < MM; m++) {
            int pp = p[m] + 1;                       // OFFSET
            float x = seq[(i * LN + pp) * DD + k];
            if (mk[m] <= 0.0f) x = -FLT_MAX;
            v[m] = x;
            mx = fmaxf(mx, x);
        }
        float s = 0.0f;
#pragma unroll
        for (int m = 0; m < MM; m++) s += expf(v[m] - mx);
        g_e_emb[idx] = mx + logf(s);
    }
}

// ---------------------------------------------------------------------------
// Kernel 2: ht_att (L2-bound) || seq->fp16 split (DRAM) || hs/ts copy (DRAM).
// ---------------------------------------------------------------------------
#define NB_HT    (NMAX * RR)                                // 1024
#define NB_SPL   ((NMAX * LN * DD / 4) / 2 / 256)           // 1536
#define NB_CPY   ((NMAX * RR * (DD / 4)) / 256)             // 768

__global__ void k_mid(const float* __restrict__ seq,
                      const int*   __restrict__ hts,
                      float* __restrict__ out,
                      int n)
{
    int blk = blockIdx.x;
    int t = threadIdx.x;
    if (blk < NB_HT) {
        // ---- ht_att: one block per (i,r) ----
        int b = blk;
        int i = b / RR;
        if (i >= n) return;
        int ha = hts[b * 2 + 0];
        int ta = hts[b * 2 + 1];

        const uint2* A = (const uint2*)(g_e_att + (size_t)(i * EE + ha) * HH * LN);
        const uint2* B = (const uint2*)(g_e_att + (size_t)(i * EE + ta) * HH * LN);

        float4 s = make_float4(0.f, 0.f, 0.f, 0.f);
#pragma unroll
        for (int hh = 0; hh < HH; hh++) {
            uint2 ua = A[hh * (LN / 4) + t];
            uint2 ub = B[hh * (LN / 4) + t];
            float2 a01 = __half22float2(*(__half2*)&ua.x);
            float2 a23 = __half22float2(*(__half2*)&ua.y);
            float2 b01 = __half22float2(*(__half2*)&ub.x);
            float2 b23 = __half22float2(*(__half2*)&ub.y);
            s.x += a01.x * b01.x; s.y += a01.y * b01.y;
            s.z += a23.x * b23.x; s.w += a23.y * b23.y;
        }
        const float invH = 1.0f / (float)HH;
        s.x *= invH; s.y *= invH; s.z *= invH; s.w *= invH;
        float local = s.x + s.y + s.z + s.w;

        __shared__ float red[8];
#pragma unroll
        for (int off = 16; off > 0; off >>= 1)
            local += __shfl_xor_sync(0xffffffffu, local, off);
        if ((t & 31) == 0) red[t >> 5] = local;
        __syncthreads();
        if (t < 32) {
            float x = (t < 8) ? red[t] : 0.0f;
#pragma unroll
            for (int off = 4; off > 0; off >>= 1)
                x += __shfl_xor_sync(0xffffffffu, x, off);
            if (t == 0) red[0] = x;
        }
        __syncthreads();
        float inv = 1.0f / (red[0] + 1e-5f);

        __half2 h01 = __floats2half2_rn(s.x * inv, s.y * inv);
        __half2 h23 = __floats2half2_rn(s.z * inv, s.w * inv);
        uint2 w;
        w.x = *(unsigned*)&h01;
        w.y = *(unsigned*)&h23;
        ((uint2*)(g_A + (size_t)b * LN))[t] = w;
    } else if (blk < NB_HT + NB_SPL) {
        // ---- seq -> fp16 (2 float4 per thread) ----
        int half_n = n * LN * DD / 4 / 2;
        int idx = (blk - NB_HT) * 256 + t;
        if (idx >= half_n) return;
#pragma unroll
        for (int u = 0; u < 2; u++) {
            int id = idx + u * half_n;
            float4 v = ((const float4*)seq)[id];
            __half2 h01 = __floats2half2_rn(v.x, v.y);
            __half2 h23 = __floats2half2_rn(v.z, v.w);
            uint2 w;
            w.x = *(unsigned*)&h01;
            w.y = *(unsigned*)&h23;
            ((uint2*)g_B)[id] = w;
        }
    } else {
        // ---- hs/ts plane copy (e_emb ready from k_eatt) ----
        int idx = (blk - NB_HT - NB_SPL) * 256 + t;    // over n*R*(D/4)
        int total = n * RR * (DD / 4);
        if (idx >= total) return;
        int c4 = idx % (DD / 4);
        int b  = idx / (DD / 4);           // i*R + r
        int i  = b / RR;
        int ha = hts[b * 2 + 0];
        int ta = hts[b * 2 + 1];
        const float4* emb4 = (const float4*)g_e_emb;
        float4* out4 = (float4*)out;
        size_t P4 = (size_t)n * RR * (DD / 4);
        out4[idx]      = emb4[(size_t)(i * EE + ha) * (DD / 4) + c4];
        out4[P4 + idx] = emb4[(size_t)(i * EE + ta) * (DD / 4) + c4];
    }
}

// ---------------------------------------------------------------------------
// Kernel 3: rs plane GEMM, plain fp16 x fp16 -> fp32 (R14 proven config,
// hs/ts copy removed). Block 64x96, BK=64, 8 warps 4(M)x2(N), 3 accs.
// Double-buffered smem, register prefetch. grid = 8x4x4 = 128 blocks.
// ---------------------------------------------------------------------------
#define GBM 64
#define GBN 96
#define GBK 64
#define GT  256
#define LDA (GBK + 8)    // 72 halves
#define LDB (GBN + 8)    // 104 halves

__global__ __launch_bounds__(GT, 1) void k_gemm(float* __restrict__ out, int n)
{
    __shared__ __align__(16) __half As[2][GBM][LDA];
    __shared__ __align__(16) __half Bs[2][GBK][LDB];

    int i = blockIdx.z;
    const __half* Ad = g_A + (size_t)i * RR * LN;
    const __half* Bd = g_B + (size_t)i * LN * DD;
    size_t P = (size_t)n * RR * DD;
    float* Cd = out + 2 * P + (size_t)i * RR * DD;      // R x D

    int rowBase = blockIdx.y * GBM;
    int colBase = blockIdx.x * GBN;
    int tid = threadIdx.x;
    int w   = tid >> 5;
    int wm  = w & 3;          // 0..3 : M slice (16 rows)
    int wn  = w >> 2;         // 0..1 : N slice (48 cols)

    // ---- loader slots (uint4 = 8 halves) ----
    int aR[2], aK[2];
#pragma unroll
    for (int s = 0; s < 2; s++) {
        int id = tid + s * GT;
        aR[s] = id >> 3; aK[s] = (id & 7) * 8;
    }
    int bR[3], bN[3];
#pragma unroll
    for (int s = 0; s < 3; s++) {
        int id = tid + s * GT;
        bR[s] = id / 12; bN[s] = (id % 12) * 8;
    }

    wmma::fragment<wmma::accumulator, 16, 16, 16, float> acc[3];
#pragma unroll
    for (int j = 0; j < 3; j++) wmma::fill_fragment(acc[j], 0.0f);

    uint4 ra[2], rb[3];
#pragma unroll
    for (int s = 0; s < 2; s++)
        ra[s] = *(const uint4*)&Ad[(size_t)(rowBase + aR[s]) * LN + aK[s]];
#pragma unroll
    for (int s = 0; s < 3; s++)
        rb[s] = *(const uint4*)&Bd[(size_t)bR[s] * DD + colBase + bN[s]];

    int buf = 0;
    for (int k0 = 0; k0 < LN; k0 += GBK) {
#pragma unroll
        for (int s = 0; s < 2; s++)
            *(uint4*)&As[buf][aR[s]][aK[s]] = ra[s];
#pragma unroll
        for (int s = 0; s < 3; s++)
            *(uint4*)&Bs[buf][bR[s]][bN[s]] = rb[s];
        __syncthreads();

        int kn = k0 + GBK;
        if (kn < LN) {
#pragma unroll
            for (int s = 0; s < 2; s++)
                ra[s] = *(const uint4*)&Ad[(size_t)(rowBase + aR[s]) * LN + kn + aK[s]];
#pragma unroll
            for (int s = 0; s < 3; s++)
                rb[s] = *(const uint4*)&Bd[(size_t)(kn + bR[s]) * DD + colBase + bN[s]];
        }

#pragma unroll
        for (int kk = 0; kk < GBK / 16; kk++) {
            wmma::fragment<wmma::matrix_a, 16, 16, 16, __half, wmma::row_major> fa;
            wmma::fragment<wmma::matrix_b, 16, 16, 16, __half, wmma::row_major> fb[3];
            wmma::load_matrix_sync(fa, &As[buf][wm * 16][kk * 16], LDA);
#pragma unroll
            for (int j = 0; j < 3; j++)
                wmma::load_matrix_sync(fb[j], &Bs[buf][kk * 16][wn * 48 + j * 16], LDB);
#pragma unroll
            for (int j = 0; j < 3; j++)
                wmma::mma_sync(acc[j], fa, fb[j], acc[j]);
        }
        buf ^= 1;
        __syncthreads();
    }

#pragma unroll
    for (int j = 0; j < 3; j++) {
        float* c = &Cd[(size_t)(rowBase + wm * 16) * DD + colBase + wn * 48 + j * 16];
        wmma::store_matrix_sync(c, acc[j], DD, wmma::mem_row_major);
    }
}

// ---------------------------------------------------------------------------
extern "C" void kernel_launch(void* const* d_in, const int* in_sizes, int n_in,
                              void* d_out, int out_size)
{
    const float* seq  = (const float*)d_in[0];   // (n, L, d)
    const float* att  = (const float*)d_in[1];   // (n, h, L, L)
    const int*   pos  = (const int*)  d_in[2];   // (n, E, M)
    const float* mask = (const float*)d_in[3];   // (n, E, M)
    const int*   hts  = (const int*)  d_in[4];   // (n, R, 2)
    float* out = (float*)d_out;

    int n = in_sizes[0] / (LN * DD);
    if (n > NMAX) n = NMAX;

    {   // k1: e_att gather || e_emb
        k_eatt<<<NB_EATT + NB_EMB, 256>>>(seq, att, pos, mask, n);
    }
    {   // k2: ht_att || seq->fp16 || hs/ts copy
        k_mid<<<NB_HT + NB_SPL + NB_CPY, 256>>>(seq, hts, out, n);
    }
    {   // k3: rs plane GEMM
        dim3 grid(DD / GBN, RR / GBM, n);
        k_gemm<<<grid, GT>>>(out, n);
    }
}